// round 17
// baseline (speedup 1.0000x reference)
#include <cuda_runtime.h>
#include <math.h>

// Fixed shapes from setup_inputs
#define BSZ 32
#define TT  50
#define CC  80
#define AA  85          // 5 + C
#define HH  76
#define WW  76
#define HWX (HH*WW)     // 5776
#define SIGMA_F 8.0f

#define BLK    256
#define NWARP  (BLK/32)                    // 8
#define BILP   2
#define CHUNK  (BLK*BILP)                  // 512
#define GXB    ((HWX + CHUNK - 1) / CHUNK) // 12 grid-role x-slices
#define OBJS   4                           // obj-role blocks per batch
#define GXT    (GXB + OBJS)                // 16
#define NBLOCKS (GXT * BSZ)                // 512

// ---------------- device scratch ----------------
__device__ int    g_neff[BSZ];
__device__ double g_noobj[16];
__device__ double g_acc[7];      // [0..3]=x,y,w,h [4]=conf_obj [5]=noobj_corr [6]=cls
__device__ unsigned int g_done;

// ---------------- math helpers ----------------
// robust softplus = log(1+exp(v)) = -clog(1-sigmoid(v)) = -clog(sigmoid(-v))
__device__ __forceinline__ float softplus_(float v) {
    return fmaxf(v, 0.0f) + __logf(1.0f + __expf(-fabsf(v)));
}
__device__ __forceinline__ float sigmoidf_(float v) {
    return __fdividef(1.0f, 1.0f + __expf(-v));
}
// bce(sigmoid(v), t) = t*softplus(-v) + (1-t)*softplus(v)
__device__ __forceinline__ float bce_logit_(float v, float t) {
    return t * softplus_(-v) + (1.0f - t) * softplus_(v);
}
__device__ __forceinline__ float sl1f_(float a, float b) {
    float d = fabsf(a - b);
    return (d < 1.0f) ? 0.5f * d * d : d - 0.5f;
}

// ---------------- single kernel, role-split blocks ----------------
__global__ __launch_bounds__(BLK) void yolo_one(const float* __restrict__ inp,
                                                const float* __restrict__ targets,
                                                float* __restrict__ out) {
    // compacted effective targets (DETERMINISTIC order by original index)
    // s_box = {3*gx1, gy1, 3*gx2, gy2}  (x pre-scaled by 3 folds the IoU>=0.5 factor)
    __shared__ float4 s_box[TT];
    __shared__ float  s_a[TT];
    __shared__ int    s_cell[TT];                                       // obj role only
    __shared__ float  s_tx[TT], s_ty[TT], s_tw[TT], s_th[TT], s_sc[TT]; // obj role only
    __shared__ int    s_cls[TT];                                        // obj role only
    // prep temporaries
    __shared__ int      s_key[32];
    __shared__ unsigned s_mask[2];
    __shared__ float    s_acc[7];

    const int bx  = blockIdx.x;   // 0..GXB-1 grid role, GXB..GXT-1 obj role
    const int b   = blockIdx.y;
    const int tid = threadIdx.x;
    const int wid  = tid >> 5;
    const int lane = tid & 31;
    const bool gridrole = (bx < GXB);

    if (!gridrole && tid < 7) s_acc[tid] = 0.0f;

    const float* bbase = inp + (size_t)b * AA * HWX;

    // ---- grid-role channel loads first (overlap with everything below) ----
    const int c0 = bx * CHUNK + 2 * tid;   // cells c0, c0+1 (HWX even)
    bool cval = false;
    float2 V0, V1, V2, V3, V4;
    if (gridrole) {
        cval = (c0 < HWX);
        const int cc = cval ? c0 : 0;
        V0 = *(const float2*)(bbase + cc);
        V1 = *(const float2*)(bbase + (size_t)1 * HWX + cc);
        V2 = *(const float2*)(bbase + (size_t)2 * HWX + cc);
        V3 = *(const float2*)(bbase + (size_t)3 * HWX + cc);
        V4 = *(const float2*)(bbase + (size_t)4 * HWX + cc);
    }

    // ---- prep on warps 0-1 only (named barriers; warps 2-7 fly past) ----
    float gx = 0.f, gy = 0.f, gw = 0.f, gh = 0.f, t0 = 0.f, t3 = 0.f, t4 = 0.f;
    int gi = 0, gj = 0, mycell = 0;
    if (tid < 64) {
        bool valid = false;
        if (tid < TT) {
            const float* tg = targets + ((size_t)b * TT + tid) * 5;
            t0 = tg[0];
            float t1 = tg[1], t2 = tg[2];
            t3 = tg[3]; t4 = tg[4];
            valid = ((t0 + t1 + t2 + t3 + t4) != 0.0f);
            gx = t1 * (float)WW;
            gy = t2 * (float)HH;
            gw = t3 * (float)WW;
            gh = t4 * (float)HH;
            gi = min(max((int)gx, 0), WW - 1);
            gj = min(max((int)gy, 0), HH - 1);
            mycell = gj * WW + gi;
        }
        if (wid == 0) s_key[lane] = valid ? mycell : -1;
        asm volatile("bar.sync 1, 64;" ::: "memory");

        // dup check (deterministic): first occurrence among VALID targets wins
        bool eff = false;
        if (wid == 0) {
            int key = valid ? mycell : (0x10000 + lane);
            unsigned mm = __match_any_sync(0xffffffffu, key);
            eff = valid && ((mm & ((1u << lane) - 1u)) == 0u);
        } else {
            int key = valid ? mycell : (0x20000 + lane);
            unsigned mm = __match_any_sync(0xffffffffu, key);
            bool dup = ((mm & ((1u << lane) - 1u)) != 0u);
            if (valid && !dup) {
                #pragma unroll 8
                for (int k = 0; k < 32; k++) dup |= (s_key[k] == mycell);
            }
            eff = valid && !dup;
        }
        unsigned m = __ballot_sync(0xffffffffu, eff);
        if (lane == 0) s_mask[wid] = m;
        asm volatile("bar.sync 2, 64;" ::: "memory");

        if (eff) {
            const unsigned m0 = s_mask[0];
            int p = (wid == 0) ? __popc(m0 & ((1u << lane) - 1u))
                               : __popc(m0) + __popc(s_mask[1] & ((1u << lane) - 1u));
            // x coords pre-scaled by 3
            float gx3 = 3.0f * gx;
            float gw3 = 3.0f * gw;
            s_box[p] = make_float4(fmaf(gw3, -0.5f, gx3), fmaf(gh, -0.5f, gy),
                                   fmaf(gw3,  0.5f, gx3), fmaf(gh,  0.5f, gy));
            s_a[p]   = gw * gh;
            if (!gridrole) {   // obj-only fields
                s_cell[p]= mycell;
                s_tx[p]  = gx - (float)gi;
                s_ty[p]  = gy - (float)gj;
                s_tw[p]  = __logf(gw / SIGMA_F + 1e-16f);
                s_th[p]  = __logf(gh / SIGMA_F + 1e-16f);
                s_sc[p]  = 2.0f - t3 * t4;
                s_cls[p] = min(max((int)t0, 0), CC - 1);
            }
        }
    }

    // ---- box setup + hoisted softplus (warps 2-7 do this while 0-1 prep) ----
    float pae[BILP], sp[BILP];
    float px1[BILP], px2[BILP], py1[BILP], py2[BILP];   // x pre-scaled by 3
    if (gridrole) {
        const int cc = cval ? c0 : 0;
        const float v0s[BILP] = {V0.x, V0.y};
        const float v1s[BILP] = {V1.x, V1.y};
        const float v2s[BILP] = {V2.x, V2.y};
        const float v3s[BILP] = {V3.x, V3.y};
        const float v4s[BILP] = {V4.x, V4.y};
        #pragma unroll
        for (int u = 0; u < BILP; u++) {
            int cell = cc + u;
            float xs = sigmoidf_(v0s[u]);
            float ys = sigmoidf_(v1s[u]);
            int i = cell % WW;
            int j = cell / WW;
            float px3 = 3.0f * (xs + (float)i);
            float py  = ys + (float)j;
            float pw  = __expf(v2s[u]) * SIGMA_F;
            float ph  = __expf(v3s[u]) * SIGMA_F;
            px1[u] = fmaf(pw, -1.5f, px3); px2[u] = fmaf(pw, 1.5f, px3);
            py1[u] = fmaf(ph, -0.5f, py);  py2[u] = fmaf(ph, 0.5f, py);
            pae[u] = pw * ph + 1e-16f;
            sp[u]  = softplus_(v4s[u]);    // hoisted; selected after the loop
        }
    }
    __syncthreads();   // single full barrier: SMEM target data ready
    const int ne = __popc(s_mask[0]) + __popc(s_mask[1]);

    if (gridrole) {
        // ================= grid role: uniform noobj + ignore =================
        float m_a[BILP], m_b[BILP];
        #pragma unroll
        for (int u = 0; u < BILP; u++) { m_a[u] = -1e30f; m_b[u] = -1e30f; }

        int e = 0;
        for (; e + 1 < ne; e += 2) {
            float4 ba = s_box[e];
            float4 bb = s_box[e + 1];
            float  eaa = s_a[e];
            float  eab = s_a[e + 1];
            #pragma unroll
            for (int u = 0; u < BILP; u++) {
                float iw0 = fminf(ba.z, px2[u]) - fmaxf(ba.x, px1[u]);  // = 3*iw
                float ih0 = fminf(ba.w, py2[u]) - fmaxf(ba.y, py1[u]);
                float iw1 = fminf(bb.z, px2[u]) - fmaxf(bb.x, px1[u]);
                float ih1 = fminf(bb.w, py2[u]) - fmaxf(bb.y, py1[u]);
                iw0 = fmaxf(iw0, 0.0f); ih0 = fmaxf(ih0, 0.0f);
                iw1 = fmaxf(iw1, 0.0f); ih1 = fmaxf(ih1, 0.0f);
                // iou >= 0.5 <=> 3*inter - ga >= pa + 1e-16
                m_a[u] = fmaxf(m_a[u], fmaf(iw0, ih0, -eaa));
                m_b[u] = fmaxf(m_b[u], fmaf(iw1, ih1, -eab));
            }
            // warp-level early exit every 4 pairs (8 targets): the ignore
            // booleans are monotone in e, so breaking cannot change results.
            if ((e & 6) == 6) {
                bool done = !cval ||
                            ((fmaxf(m_a[0], m_b[0]) >= pae[0]) &&
                             (fmaxf(m_a[1], m_b[1]) >= pae[1]));
                if (__all_sync(0xffffffffu, done)) break;
            }
        }
        if (e + 1 == ne) {   // odd tail (only if not broken out early)
            float4 ba = s_box[e];
            float  ea = s_a[e];
            #pragma unroll
            for (int u = 0; u < BILP; u++) {
                float iw = fminf(ba.z, px2[u]) - fmaxf(ba.x, px1[u]);
                float ih = fminf(ba.w, py2[u]) - fmaxf(ba.y, py1[u]);
                iw = fmaxf(iw, 0.0f); ih = fmaxf(ih, 0.0f);
                m_a[u] = fmaxf(m_a[u], fmaf(iw, ih, -ea));
            }
        }

        float acc = 0.0f;
        #pragma unroll
        for (int u = 0; u < BILP; u++) {
            float m = fmaxf(m_a[u], m_b[u]);
            if (cval && (m < pae[u])) acc += sp[u];
        }

        #pragma unroll
        for (int o = 16; o > 0; o >>= 1) acc += __shfl_down_sync(0xffffffffu, acc, o);
        // per-warp global atomic: no shared stage, no tail barrier
        if (lane == 0 && acc != 0.0f)
            atomicAdd(&g_noobj[((b * GXB + bx) * NWARP + wid) & 15], (double)acc);
    } else {
        // ================= obj role: OBJS blocks per batch, warp per target =================
        const int slice = bx - GXB;          // 0..OBJS-1
        if (slice == 0 && tid == 0) g_neff[b] = ne;

        for (int e = slice * NWARP + wid; e < ne; e += OBJS * NWARP) {
            const int cell = s_cell[e];
            const float* base = bbase + cell;

            float v0 = base[0];
            float v1 = base[(size_t)1 * HWX];
            float v2 = base[(size_t)2 * HWX];
            float v3 = base[(size_t)3 * HWX];
            float v4 = base[(size_t)4 * HWX];

            // identical pred-box expressions as grid role -> identical ignore test
            float xs = sigmoidf_(v0);
            float ys = sigmoidf_(v1);
            int i = cell % WW;
            int j = cell / WW;
            float px3 = 3.0f * (xs + (float)i);
            float py  = ys + (float)j;
            float pw  = __expf(v2) * SIGMA_F;
            float ph  = __expf(v3) * SIGMA_F;
            float opx1 = fmaf(pw, -1.5f, px3), opx2 = fmaf(pw, 1.5f, px3);
            float opy1 = fmaf(ph, -0.5f, py),  opy2 = fmaf(ph, 0.5f, py);
            float opae = pw * ph + 1e-16f;

            bool ig = false;
            for (int k = lane; k < ne; k += 32) {
                float4 bk = s_box[k];
                float iw = fminf(bk.z, opx2) - fmaxf(bk.x, opx1);
                float ih = fminf(bk.w, opy2) - fmaxf(bk.y, opy1);
                iw = fmaxf(iw, 0.0f);
                ih = fmaxf(ih, 0.0f);
                ig |= (fmaf(iw, ih, -s_a[k]) >= opae);
            }
            ig = (__ballot_sync(0xffffffffu, ig) != 0u);

            // class BCE lane-parallel over 80 classes (scattered loads, MLP across lanes)
            const int cls = s_cls[e];
            float scl = 0.0f;
            for (int c = lane; c < CC; c += 32) {
                float vc = base[(size_t)(5 + c) * HWX];
                scl += (c == cls) ? softplus_(-vc) : softplus_(vc);
            }
            #pragma unroll
            for (int o = 16; o > 0; o >>= 1) scl += __shfl_down_sync(0xffffffffu, scl, o);

            if (lane == 0) {
                float sc = s_sc[e];
                atomicAdd(&s_acc[0], sc * bce_logit_(v0, s_tx[e]));
                atomicAdd(&s_acc[1], sc * bce_logit_(v1, s_ty[e]));
                atomicAdd(&s_acc[2], sc * sl1f_(v2, s_tw[e]));
                atomicAdd(&s_acc[3], sc * sl1f_(v3, s_th[e]));
                atomicAdd(&s_acc[4], softplus_(-v4));          // -clog(conf) at obj cell
                if (!ig) atomicAdd(&s_acc[5], softplus_(v4));  // noobj over-count correction
                atomicAdd(&s_acc[6], scl);
            }
        }
        __syncthreads();
        if (tid < 7 && s_acc[tid] != 0.0f) atomicAdd(&g_acc[tid], (double)s_acc[tid]);
    }

    // ---- finalize in the last-arriving block ----
    __shared__ bool s_last;
    if (tid == 0) {
        __threadfence();
        unsigned int ticket = atomicAdd(&g_done, 1u);
        s_last = (ticket == (unsigned int)(NBLOCKS - 1));
    }
    __syncthreads();
    if (s_last && tid == 0) {
        __threadfence();
        volatile double* acc = g_acc;
        int nobj = 0;
        for (int k = 0; k < BSZ; k++) nobj += g_neff[k];
        double noobj_sum = 0.0;
        for (int k = 0; k < 16; k++) noobj_sum += g_noobj[k];
        double inv = 1.0 / (double)nobj;
        double lx = acc[0] * inv;
        double ly = acc[1] * inv;
        double lw = acc[2] * inv;
        double lh = acc[3] * inv;
        double lconf = (acc[4] + 0.5 * (noobj_sum - acc[5])) * inv;
        double lcls  = (nobj > 0) ? acc[6] * inv : 0.0;  // sum(tcls) == n_obj
        double loss = lx + ly + lw + lh + lconf + lcls;
        out[0] = (float)loss;
        out[1] = (float)lx;
        out[2] = (float)ly;
        out[3] = (float)lw;
        out[4] = (float)lh;
        out[5] = (float)lconf;
        out[6] = (float)lcls;
        // reset for next graph replay
        for (int k = 0; k < 7;  k++) g_acc[k]   = 0.0;
        for (int k = 0; k < 16; k++) g_noobj[k] = 0.0;
        g_done = 0u;
    }
}

// ---------------- launch ----------------
extern "C" void kernel_launch(void* const* d_in, const int* in_sizes, int n_in,
                              void* d_out, int out_size) {
    const float* inp     = (const float*)d_in[0];   // [32, 85, 76, 76]
    const float* targets = (const float*)d_in[1];   // [32, 50, 5]
    float* out = (float*)d_out;

    dim3 grid(GXT, BSZ);
    yolo_one<<<grid, BLK>>>(inp, targets, out);
}